// round 15
// baseline (speedup 1.0000x reference)
#include <cuda_runtime.h>
#include <cuda_bf16.h>
#include <math.h>

#define N_SRC 10000
#define N_DST 40000
#define NE    1280000
#define IN_DIM 128
#define O_DIM  300
#define FEAT   64
#define D      64

// ---------------- scratch (static device globals) ----------------
__device__ float    g_zsrc[N_SRC * D];
__device__ unsigned g_zsrc_h[N_SRC * 32];   // bf16x2 pairs (L2-resident)
__device__ unsigned g_zdst_h[N_DST * 32];   // bf16x2 pairs (L2-resident)
__device__ float    g_e[NE];                // exp(logit) in CSR order
__device__ int      g_cnt[N_DST];
__device__ int      g_start[N_DST];
__device__ int      g_cur[N_DST];
__device__ int      g_eid[NE];              // csr position -> edge id
__device__ int      g_srcs[NE];             // src id in CSR order
__device__ int      g_dsts[NE];             // dst id in CSR order
__device__ int      g_bsum[64];
__device__ unsigned g_Wfb[32 * 64];         // W_feat bf16 pairs [kpair][n]
__device__ unsigned g_Wfb1[152 * 64];       // W_fc1 bf16 pairs, k padded

__device__ __forceinline__ unsigned pack_bf16(float lo, float hi) {
    unsigned u;
    asm("cvt.rn.bf16x2.f32 %0, %1, %2;" : "=r"(u) : "f"(hi), "f"(lo));
    return u;
}
__device__ __forceinline__ float2 unpack_bf16(unsigned u) {
    __nv_bfloat162 b = *(__nv_bfloat162*)&u;
    return __bfloat1622float2(b);
}
__device__ __forceinline__ void cp_async16(void* smem_dst, const void* gmem_src) {
    unsigned saddr = (unsigned)__cvta_generic_to_shared(smem_dst);
    asm volatile("cp.async.cg.shared.global [%0], [%1], 16;"
                 :: "r"(saddr), "l"(gmem_src) : "memory");
}
__device__ __forceinline__ void cp_async_wait_all() {
    asm volatile("cp.async.commit_group;\ncp.async.wait_group 0;" ::: "memory");
}

#define MMA_BF16(acc, a0, a1, a2, a3, b0, b1)                                        \
    asm volatile("mma.sync.aligned.m16n8k16.row.col.f32.bf16.bf16.f32 "              \
                 "{%0,%1,%2,%3}, {%4,%5,%6,%7}, {%8,%9}, {%0,%1,%2,%3};"             \
                 : "+f"(acc[0]), "+f"(acc[1]), "+f"(acc[2]), "+f"(acc[3])            \
                 : "r"(a0), "r"(a1), "r"(a2), "r"(a3), "r"(b0), "r"(b1))

// ---------------- K1: setup = zero cnt + pack weights ----------------
__global__ void __launch_bounds__(256) setup_kernel(const float* __restrict__ Wfeat,
                                                    const float* __restrict__ Wfc1) {
    int b = blockIdx.x;
    int tid = threadIdx.x;
    if (b < 157) {
        int i = b * 256 + tid;
        if (i < N_DST) g_cnt[i] = 0;
    } else if (b < 165) {
        int i = (b - 157) * 256 + tid;
        int kp = i >> 6, n = i & 63;
        g_Wfb[i] = pack_bf16(Wfeat[(2 * kp) * 64 + n], Wfeat[(2 * kp + 1) * 64 + n]);
    } else {
        int i = (b - 165) * 256 + tid;
        if (i < 152 * 64) {
            int kp = i >> 6, n = i & 63;
            int k0 = 2 * kp, k1 = 2 * kp + 1;
            float lo = (k0 < O_DIM) ? Wfc1[k0 * 64 + n] : 0.f;
            float hi = (k1 < O_DIM) ? Wfc1[k1 * 64 + n] : 0.f;
            g_Wfb1[i] = pack_bf16(lo, hi);
        }
    }
}

// ---------------- K2: count || zsrc || zdst (grid-merged) ----------------
#define CB_COUNT 5000
#define CB_ZSRC  625
#define CB_ZDST  625

struct SmemZsrc { float sW[IN_DIM][D]; float sh[16][IN_DIM]; };
struct SmemZdst { unsigned sA[64][84]; unsigned sW[80][72]; };
union SmemK2 { SmemZsrc zs; SmemZdst zd; };

__device__ __forceinline__ void do_zsrc(const float* __restrict__ h,
                                        const float* __restrict__ W,
                                        SmemZsrc& sm, int b, int tid) {
    int r0 = b * 16;
    for (int i = tid; i < IN_DIM * D / 4; i += 256)
        ((float4*)&sm.sW[0][0])[i] = ((const float4*)W)[i];
    for (int i = tid; i < 16 * IN_DIM / 4; i += 256)
        ((float4*)&sm.sh[0][0])[i] = ((const float4*)(h + (size_t)r0 * IN_DIM))[i];
    __syncthreads();
    int d4 = (tid & 15) * 4;
    int r  = tid >> 4;
    float a0 = 0.f, a1 = 0.f, a2 = 0.f, a3 = 0.f;
#pragma unroll 8
    for (int k = 0; k < IN_DIM; k++) {
        float hv = sm.sh[r][k];
        float4 w = *(const float4*)&sm.sW[k][d4];
        a0 += hv * w.x; a1 += hv * w.y; a2 += hv * w.z; a3 += hv * w.w;
    }
    int node = r0 + r;
    *(float4*)&g_zsrc[(size_t)node * D + d4] = make_float4(a0, a1, a2, a3);
    *(uint2*)&g_zsrc_h[(size_t)node * 32 + d4 / 2] =
        make_uint2(pack_bf16(a0, a1), pack_bf16(a2, a3));
}

__device__ __forceinline__ void do_zdst(const float* __restrict__ o,
                                        SmemZdst& sm, int b, int tid) {
    int lane = tid & 31, warp = tid >> 5;
    int r0 = b * 64;
    int g = lane >> 2, qp = lane & 3;
    int mt = warp & 3;
    int nh = warp >> 2;

    float acc[4][4];
#pragma unroll
    for (int nt = 0; nt < 4; nt++)
        acc[nt][0] = acc[nt][1] = acc[nt][2] = acc[nt][3] = 0.f;

    for (int c = 0; c < 2; c++) {
        int kp0 = c * 80;
        __syncthreads();
        for (int i = tid; i < 64 * 80; i += 256) {
            int row = i / 80, kp = i % 80;
            int gkp = kp0 + kp;
            float lo = 0.f, hi = 0.f;
            if (gkp < 150) {
                float2 v = *(const float2*)&o[(size_t)(r0 + row) * O_DIM + gkp * 2];
                lo = v.x; hi = v.y;
            }
            sm.sA[row][kp] = pack_bf16(lo, hi);
        }
        int npair = c ? 72 : 80;
        for (int i = tid; i < npair * 64; i += 256) {
            int kp = i >> 6, n = i & 63;
            sm.sW[kp][n] = g_Wfb1[(kp0 + kp) * 64 + n];
        }
        __syncthreads();
        int nkt = c ? 9 : 10;
        for (int lt = 0; lt < nkt; lt++) {
            unsigned a0 = sm.sA[mt * 16 + g][lt * 8 + qp];
            unsigned a1 = sm.sA[mt * 16 + g + 8][lt * 8 + qp];
            unsigned a2 = sm.sA[mt * 16 + g][lt * 8 + qp + 4];
            unsigned a3 = sm.sA[mt * 16 + g + 8][lt * 8 + qp + 4];
#pragma unroll
            for (int nt = 0; nt < 4; nt++) {
                int nn = (nh * 4 + nt) * 8 + g;
                unsigned b0 = sm.sW[lt * 8 + qp][nn];
                unsigned b1 = sm.sW[lt * 8 + qp + 4][nn];
                MMA_BF16(acc[nt], a0, a1, a2, a3, b0, b1);
            }
        }
    }
    int row0 = r0 + mt * 16 + g;
#pragma unroll
    for (int nt = 0; nt < 4; nt++) {
        int pair = (nh * 4 + nt) * 4 + qp;
        g_zdst_h[(size_t)row0 * 32 + pair]       = pack_bf16(acc[nt][0], acc[nt][1]);
        g_zdst_h[(size_t)(row0 + 8) * 32 + pair] = pack_bf16(acc[nt][2], acc[nt][3]);
    }
}

__global__ void __launch_bounds__(256) fused_k2_kernel(const int* __restrict__ edst,
                                                       const float* __restrict__ h,
                                                       const float* __restrict__ W_fc,
                                                       const float* __restrict__ o) {
    __shared__ SmemK2 sm;
    int b = blockIdx.x, tid = threadIdx.x;
    if (b < CB_COUNT) {
        int i = b * 256 + tid;
        if (i < NE) atomicAdd(&g_cnt[edst[i]], 1);
    } else if (b < CB_COUNT + CB_ZSRC) {
        do_zsrc(h, W_fc, sm.zs, b - CB_COUNT, tid);
    } else {
        do_zdst(o, sm.zd, b - CB_COUNT - CB_ZSRC, tid);
    }
}

// ---------------- CSR scans ----------------
__global__ void __launch_bounds__(1024) scan1_kernel() {
    __shared__ int wsum[32];
    __shared__ int wpre[32];
    int tid = threadIdx.x, lane = tid & 31, wid = tid >> 5;
    int i = blockIdx.x * 1024 + tid;
    int v = (i < N_DST) ? g_cnt[i] : 0;
    int x = v;
#pragma unroll
    for (int off = 1; off < 32; off <<= 1) {
        int t = __shfl_up_sync(0xffffffffu, x, off);
        if (lane >= off) x += t;
    }
    if (lane == 31) wsum[wid] = x;
    __syncthreads();
    if (wid == 0) {
        int s = wsum[lane];
#pragma unroll
        for (int off = 1; off < 32; off <<= 1) {
            int t = __shfl_up_sync(0xffffffffu, s, off);
            if (lane >= off) s += t;
        }
        wpre[lane] = s;
    }
    __syncthreads();
    int base = wid ? wpre[wid - 1] : 0;
    if (i < N_DST) g_start[i] = base + x - v;
    if (tid == 0) g_bsum[blockIdx.x] = wpre[31];
}
__global__ void __launch_bounds__(1024) scan3_kernel() {
    __shared__ int sbs[40];
    __shared__ int sbase;
    int tid = threadIdx.x;
    if (tid < 40) sbs[tid] = g_bsum[tid];
    __syncthreads();
    if (tid == 0) {
        int a = 0;
        int b = blockIdx.x;
        for (int t = 0; t < b; t++) a += sbs[t];
        sbase = a;
    }
    __syncthreads();
    int i = blockIdx.x * 1024 + tid;
    if (i < N_DST) {
        int st = g_start[i] + sbase;
        g_start[i] = st;
        g_cur[i]   = st;
    }
}

// ---------------- fill: 4 edges/thread for atomic MLP ----------------
__global__ void __launch_bounds__(256) fill_kernel(const int* __restrict__ dst,
                                                   const int* __restrict__ src) {
    int i0 = blockIdx.x * 1024 + threadIdx.x;   // NE = 1250 * 1024 exactly
    int i1 = i0 + 256, i2 = i0 + 512, i3 = i0 + 768;
    int d0 = dst[i0], d1 = dst[i1], d2 = dst[i2], d3 = dst[i3];
    int s0 = src[i0], s1 = src[i1], s2 = src[i2], s3 = src[i3];
    int p0 = atomicAdd(&g_cur[d0], 1);
    int p1 = atomicAdd(&g_cur[d1], 1);
    int p2 = atomicAdd(&g_cur[d2], 1);
    int p3 = atomicAdd(&g_cur[d3], 1);
    g_eid[p0] = i0; g_srcs[p0] = s0; g_dsts[p0] = d0;
    g_eid[p1] = i1; g_srcs[p1] = s1; g_dsts[p1] = d1;
    g_eid[p2] = i2; g_srcs[p2] = s2; g_dsts[p2] = d2;
    g_eid[p3] = i3; g_srcs[p3] = s3; g_dsts[p3] = d3;
}

// ---------------- edge logits: CSR order, cp.async z staging ----------------
struct SmemEdge {
    unsigned sT[128][36];   // tfidf bf16 pairs [edge][kpair]
    unsigned sW[32][72];    // W_feat bf16 pairs [kpair][n]
    unsigned sZ[128][36];   // src z bf16 pairs [edge][pair], cols 0..31
    unsigned sZD[128][36];  // dst z bf16 pairs [edge][pair], cols 0..31
    float    sP[128][2];    // partial logit dots per n-half
    int      sE[128];
    int      sS[128];
    int      sD[128];
};

__global__ void __launch_bounds__(512, 3) edge_kernel(const float* __restrict__ tfidf,
                                                      const float* __restrict__ bfeat,
                                                      const float* __restrict__ Wattn) {
    extern __shared__ char smem_raw[];
    SmemEdge& sm = *(SmemEdge*)smem_raw;
    int tid  = threadIdx.x;
    int base = blockIdx.x * 128;

    if (tid < 128) {
        sm.sE[tid] = g_eid[base + tid];
        sm.sS[tid] = g_srcs[base + tid];
        sm.sD[tid] = g_dsts[base + tid];
    }
    for (int i = tid; i < 32 * 64; i += 512)
        sm.sW[i >> 6][i & 63] = g_Wfb[i];
    __syncthreads();

    // issue cp.async z staging first — proceeds in background through tfidf phase
    for (int i = tid; i < 128 * 8; i += 512) {
        int end = i >> 3, c = i & 7;
        cp_async16(&sm.sZ[end][c * 4], &g_zsrc_h[(size_t)sm.sS[end] * 32 + c * 4]);
    }
    for (int i = tid; i < 128 * 8; i += 512) {
        int end = i >> 3, c = i & 7;
        cp_async16(&sm.sZD[end][c * 4], &g_zdst_h[(size_t)sm.sD[end] * 32 + c * 4]);
    }

    // tfidf staging (register path: needs f32 -> bf16 cvt), overlaps cp.asyncs
    for (int i = tid; i < 128 * 16; i += 512) {
        int row = i >> 4, c4 = i & 15;
        float4 v = *(const float4*)&tfidf[(size_t)sm.sE[row] * FEAT + c4 * 4];
        sm.sT[row][c4 * 2]     = pack_bf16(v.x, v.y);
        sm.sT[row][c4 * 2 + 1] = pack_bf16(v.z, v.w);
    }
    cp_async_wait_all();
    __syncthreads();

    int lane = tid & 31, warp = tid >> 5;
    int g = lane >> 2, qp = lane & 3;
    int mt = warp & 7;       // m-tile: 16 edges
    int nh = warp >> 3;      // n-half: 32 cols
    int wb = mt * 16;

    float acc[4][4];
#pragma unroll
    for (int nt = 0; nt < 4; nt++)
        acc[nt][0] = acc[nt][1] = acc[nt][2] = acc[nt][3] = 0.f;

#pragma unroll
    for (int kt = 0; kt < 4; kt++) {
        unsigned a0 = sm.sT[wb + g][kt * 8 + qp];
        unsigned a1 = sm.sT[wb + g + 8][kt * 8 + qp];
        unsigned a2 = sm.sT[wb + g][kt * 8 + qp + 4];
        unsigned a3 = sm.sT[wb + g + 8][kt * 8 + qp + 4];
#pragma unroll
        for (int nt = 0; nt < 4; nt++) {
            int nn = (nh * 4 + nt) * 8 + g;
            unsigned b0 = sm.sW[kt * 8 + qp][nn];
            unsigned b1 = sm.sW[kt * 8 + qp + 4][nn];
            MMA_BF16(acc[nt], a0, a1, a2, a3, b0, b1);
        }
    }

    // epilogue: conflict-free LDS for all z terms
    float p0 = 0.f, p1 = 0.f;
#pragma unroll
    for (int nt = 0; nt < 4; nt++) {
        int col  = (nh * 4 + nt) * 8 + qp * 2;
        int pair = col >> 1;
        float2 bf  = *(const float2*)&bfeat[col];
        float2 wa  = *(const float2*)&Wattn[col];
        float2 zs0 = unpack_bf16(sm.sZ[wb + g][pair]);
        float2 zs1 = unpack_bf16(sm.sZ[wb + g + 8][pair]);
        float2 zd0 = unpack_bf16(sm.sZD[wb + g][pair]);
        float2 zd1 = unpack_bf16(sm.sZD[wb + g + 8][pair]);
        float v;
        v = acc[nt][0] + zs0.x + zd0.x + bf.x; v = v > 0.f ? v : 0.01f * v; p0 += v * wa.x;
        v = acc[nt][1] + zs0.y + zd0.y + bf.y; v = v > 0.f ? v : 0.01f * v; p0 += v * wa.y;
        v = acc[nt][2] + zs1.x + zd1.x + bf.x; v = v > 0.f ? v : 0.01f * v; p1 += v * wa.x;
        v = acc[nt][3] + zs1.y + zd1.y + bf.y; v = v > 0.f ? v : 0.01f * v; p1 += v * wa.y;
    }
    p0 += __shfl_xor_sync(0xffffffffu, p0, 1);
    p0 += __shfl_xor_sync(0xffffffffu, p0, 2);
    p1 += __shfl_xor_sync(0xffffffffu, p1, 1);
    p1 += __shfl_xor_sync(0xffffffffu, p1, 2);
    if (qp == 0) {
        sm.sP[wb + g][nh]     = p0;
        sm.sP[wb + g + 8][nh] = p1;
    }
    __syncthreads();
    if (tid < 128)
        g_e[base + tid] = __expf(sm.sP[tid][0] + sm.sP[tid][1]);  // no-max softmax
}

// ---------------- single-pass softmax + aggregation (warp per dst) ----------------
__global__ void __launch_bounds__(256) agg_kernel(float* __restrict__ out) {
    int w    = (blockIdx.x * blockDim.x + threadIdx.x) >> 5;
    int lane = threadIdx.x & 31;
    if (w >= N_DST) return;
    int start = g_start[w];
    int deg   = g_cnt[w];

    float denom = 0.f, accx = 0.f, accy = 0.f;
    for (int j0 = 0; j0 < deg; j0 += 32) {
        int j = j0 + lane;
        float we = 0.f;
        int s = 0;
        if (j < deg) {
            we = g_e[start + j];       // already exp()
            s  = g_srcs[start + j];
        }
        denom += we;
        int n = min(32, deg - j0);
        int k = 0;
        for (; k + 4 <= n; k += 4) {
            float a0 = __shfl_sync(0xffffffffu, we, k);
            float a1 = __shfl_sync(0xffffffffu, we, k + 1);
            float a2 = __shfl_sync(0xffffffffu, we, k + 2);
            float a3 = __shfl_sync(0xffffffffu, we, k + 3);
            int ss0 = __shfl_sync(0xffffffffu, s, k);
            int ss1 = __shfl_sync(0xffffffffu, s, k + 1);
            int ss2 = __shfl_sync(0xffffffffu, s, k + 2);
            int ss3 = __shfl_sync(0xffffffffu, s, k + 3);
            float2 z0 = *(const float2*)&g_zsrc[(size_t)ss0 * D + 2 * lane];
            float2 z1 = *(const float2*)&g_zsrc[(size_t)ss1 * D + 2 * lane];
            float2 z2 = *(const float2*)&g_zsrc[(size_t)ss2 * D + 2 * lane];
            float2 z3 = *(const float2*)&g_zsrc[(size_t)ss3 * D + 2 * lane];
            accx += a0 * z0.x + a1 * z1.x + a2 * z2.x + a3 * z3.x;
            accy += a0 * z0.y + a1 * z1.y + a2 * z2.y + a3 * z3.y;
        }
        for (; k < n; k++) {
            float a = __shfl_sync(0xffffffffu, we, k);
            int  ss = __shfl_sync(0xffffffffu, s, k);
            float2 z = *(const float2*)&g_zsrc[(size_t)ss * D + 2 * lane];
            accx += a * z.x;
            accy += a * z.y;
        }
    }
#pragma unroll
    for (int off = 16; off; off >>= 1) denom += __shfl_xor_sync(0xffffffffu, denom, off);
    float inv = 1.0f / fmaxf(denom, 1e-9f);
    *(float2*)&out[(size_t)w * D + 2 * lane] = make_float2(accx * inv, accy * inv);
}

// ---------------- launch ----------------
extern "C" void kernel_launch(void* const* d_in, const int* in_sizes, int n_in,
                              void* d_out, int out_size) {
    const float* h      = (const float*)d_in[0];
    const float* o      = (const float*)d_in[1];
    const float* tfidf  = (const float*)d_in[2];
    const float* W_fc   = (const float*)d_in[3];
    const float* W_fc1  = (const float*)d_in[4];
    const float* W_feat = (const float*)d_in[5];
    const float* b_feat = (const float*)d_in[6];
    const float* W_attn = (const float*)d_in[7];
    const int* esrc     = (const int*)d_in[8];
    const int* edst     = (const int*)d_in[9];
    float* out = (float*)d_out;

    static bool attr_set = false;
    if (!attr_set) {
        cudaFuncSetAttribute(edge_kernel, cudaFuncAttributeMaxDynamicSharedMemorySize,
                             (int)sizeof(SmemEdge));
        attr_set = true;
    }

    setup_kernel<<<203, 256>>>(W_feat, W_fc1);
    fused_k2_kernel<<<CB_COUNT + CB_ZSRC + CB_ZDST, 256>>>(edst, h, W_fc, o);
    scan1_kernel<<<40, 1024>>>();
    scan3_kernel<<<40, 1024>>>();
    fill_kernel<<<NE / 1024, 256>>>(edst, esrc);
    edge_kernel<<<NE / 128, 512, sizeof(SmemEdge)>>>(tfidf, b_feat, W_attn);
    agg_kernel<<<(N_DST * 32 + 255) / 256, 256>>>(out);
}

// round 16
// speedup vs baseline: 1.0705x; 1.0705x over previous
#include <cuda_runtime.h>
#include <cuda_bf16.h>
#include <math.h>

#define N_SRC 10000
#define N_DST 40000
#define NE    1280000
#define IN_DIM 128
#define O_DIM  300
#define FEAT   64
#define D      64

// ---------------- scratch (static device globals) ----------------
__device__ float    g_zsrc[N_SRC * D];
__device__ unsigned g_zsrc_h[N_SRC * 32];   // bf16x2 pairs (L2-resident)
__device__ unsigned g_zdst_h[N_DST * 32];   // bf16x2 pairs (L2-resident)
__device__ float    g_e[NE];                // exp(logit) in EDGE order
__device__ int      g_cnt[N_DST];
__device__ int      g_start[N_DST];
__device__ int      g_cur[N_DST];
__device__ int      g_eid[NE];              // csr position -> edge id
__device__ int      g_srcs[NE];             // src id in CSR order
__device__ int      g_bsum[64];
__device__ unsigned g_Wfb[32 * 64];         // W_feat bf16 pairs [kpair][n]
__device__ unsigned g_Wfb1[152 * 64];       // W_fc1 bf16 pairs, k padded

__device__ __forceinline__ unsigned pack_bf16(float lo, float hi) {
    unsigned u;
    asm("cvt.rn.bf16x2.f32 %0, %1, %2;" : "=r"(u) : "f"(hi), "f"(lo));
    return u;
}
__device__ __forceinline__ float2 unpack_bf16(unsigned u) {
    __nv_bfloat162 b = *(__nv_bfloat162*)&u;
    return __bfloat1622float2(b);
}

#define MMA_BF16(acc, a0, a1, a2, a3, b0, b1)                                        \
    asm volatile("mma.sync.aligned.m16n8k16.row.col.f32.bf16.bf16.f32 "              \
                 "{%0,%1,%2,%3}, {%4,%5,%6,%7}, {%8,%9}, {%0,%1,%2,%3};"             \
                 : "+f"(acc[0]), "+f"(acc[1]), "+f"(acc[2]), "+f"(acc[3])            \
                 : "r"(a0), "r"(a1), "r"(a2), "r"(a3), "r"(b0), "r"(b1))

// ---------------- K1: setup = zero cnt + pack weights ----------------
__global__ void __launch_bounds__(256) setup_kernel(const float* __restrict__ Wfeat,
                                                    const float* __restrict__ Wfc1) {
    int b = blockIdx.x;
    int tid = threadIdx.x;
    if (b < 157) {
        int i = b * 256 + tid;
        if (i < N_DST) g_cnt[i] = 0;
    } else if (b < 165) {
        int i = (b - 157) * 256 + tid;
        int kp = i >> 6, n = i & 63;
        g_Wfb[i] = pack_bf16(Wfeat[(2 * kp) * 64 + n], Wfeat[(2 * kp + 1) * 64 + n]);
    } else {
        int i = (b - 165) * 256 + tid;
        if (i < 152 * 64) {
            int kp = i >> 6, n = i & 63;
            int k0 = 2 * kp, k1 = 2 * kp + 1;
            float lo = (k0 < O_DIM) ? Wfc1[k0 * 64 + n] : 0.f;
            float hi = (k1 < O_DIM) ? Wfc1[k1 * 64 + n] : 0.f;
            g_Wfb1[i] = pack_bf16(lo, hi);
        }
    }
}

// ---------------- K2: count || zsrc || zdst (grid-merged) ----------------
#define CB_COUNT 5000
#define CB_ZSRC  625
#define CB_ZDST  625

struct SmemZsrc { float sW[IN_DIM][D]; float sh[16][IN_DIM]; };
struct SmemZdst { unsigned sA[64][84]; unsigned sW[80][72]; };
union SmemK2 { SmemZsrc zs; SmemZdst zd; };

__device__ __forceinline__ void do_zsrc(const float* __restrict__ h,
                                        const float* __restrict__ W,
                                        SmemZsrc& sm, int b, int tid) {
    int r0 = b * 16;
    for (int i = tid; i < IN_DIM * D / 4; i += 256)
        ((float4*)&sm.sW[0][0])[i] = ((const float4*)W)[i];
    for (int i = tid; i < 16 * IN_DIM / 4; i += 256)
        ((float4*)&sm.sh[0][0])[i] = ((const float4*)(h + (size_t)r0 * IN_DIM))[i];
    __syncthreads();
    int d4 = (tid & 15) * 4;
    int r  = tid >> 4;
    float a0 = 0.f, a1 = 0.f, a2 = 0.f, a3 = 0.f;
#pragma unroll 8
    for (int k = 0; k < IN_DIM; k++) {
        float hv = sm.sh[r][k];
        float4 w = *(const float4*)&sm.sW[k][d4];
        a0 += hv * w.x; a1 += hv * w.y; a2 += hv * w.z; a3 += hv * w.w;
    }
    int node = r0 + r;
    *(float4*)&g_zsrc[(size_t)node * D + d4] = make_float4(a0, a1, a2, a3);
    *(uint2*)&g_zsrc_h[(size_t)node * 32 + d4 / 2] =
        make_uint2(pack_bf16(a0, a1), pack_bf16(a2, a3));
}

__device__ __forceinline__ void do_zdst(const float* __restrict__ o,
                                        SmemZdst& sm, int b, int tid) {
    int lane = tid & 31, warp = tid >> 5;
    int r0 = b * 64;
    int g = lane >> 2, qp = lane & 3;
    int mt = warp & 3;
    int nh = warp >> 2;

    float acc[4][4];
#pragma unroll
    for (int nt = 0; nt < 4; nt++)
        acc[nt][0] = acc[nt][1] = acc[nt][2] = acc[nt][3] = 0.f;

    for (int c = 0; c < 2; c++) {
        int kp0 = c * 80;
        __syncthreads();
        for (int i = tid; i < 64 * 80; i += 256) {
            int row = i / 80, kp = i % 80;
            int gkp = kp0 + kp;
            float lo = 0.f, hi = 0.f;
            if (gkp < 150) {
                float2 v = *(const float2*)&o[(size_t)(r0 + row) * O_DIM + gkp * 2];
                lo = v.x; hi = v.y;
            }
            sm.sA[row][kp] = pack_bf16(lo, hi);
        }
        int npair = c ? 72 : 80;
        for (int i = tid; i < npair * 64; i += 256) {
            int kp = i >> 6, n = i & 63;
            sm.sW[kp][n] = g_Wfb1[(kp0 + kp) * 64 + n];
        }
        __syncthreads();
        int nkt = c ? 9 : 10;
        for (int lt = 0; lt < nkt; lt++) {
            unsigned a0 = sm.sA[mt * 16 + g][lt * 8 + qp];
            unsigned a1 = sm.sA[mt * 16 + g + 8][lt * 8 + qp];
            unsigned a2 = sm.sA[mt * 16 + g][lt * 8 + qp + 4];
            unsigned a3 = sm.sA[mt * 16 + g + 8][lt * 8 + qp + 4];
#pragma unroll
            for (int nt = 0; nt < 4; nt++) {
                int nn = (nh * 4 + nt) * 8 + g;
                unsigned b0 = sm.sW[lt * 8 + qp][nn];
                unsigned b1 = sm.sW[lt * 8 + qp + 4][nn];
                MMA_BF16(acc[nt], a0, a1, a2, a3, b0, b1);
            }
        }
    }
    int row0 = r0 + mt * 16 + g;
#pragma unroll
    for (int nt = 0; nt < 4; nt++) {
        int pair = (nh * 4 + nt) * 4 + qp;
        g_zdst_h[(size_t)row0 * 32 + pair]       = pack_bf16(acc[nt][0], acc[nt][1]);
        g_zdst_h[(size_t)(row0 + 8) * 32 + pair] = pack_bf16(acc[nt][2], acc[nt][3]);
    }
}

__global__ void __launch_bounds__(256) fused_k2_kernel(const int* __restrict__ edst,
                                                       const float* __restrict__ h,
                                                       const float* __restrict__ W_fc,
                                                       const float* __restrict__ o) {
    __shared__ SmemK2 sm;
    int b = blockIdx.x, tid = threadIdx.x;
    if (b < CB_COUNT) {
        int i = b * 256 + tid;
        if (i < NE) atomicAdd(&g_cnt[edst[i]], 1);
    } else if (b < CB_COUNT + CB_ZSRC) {
        do_zsrc(h, W_fc, sm.zs, b - CB_COUNT, tid);
    } else {
        do_zdst(o, sm.zd, b - CB_COUNT - CB_ZSRC, tid);
    }
}

// ---------------- CSR scans ----------------
__global__ void __launch_bounds__(1024) scan1_kernel() {
    __shared__ int wsum[32];
    __shared__ int wpre[32];
    int tid = threadIdx.x, lane = tid & 31, wid = tid >> 5;
    int i = blockIdx.x * 1024 + tid;
    int v = (i < N_DST) ? g_cnt[i] : 0;
    int x = v;
#pragma unroll
    for (int off = 1; off < 32; off <<= 1) {
        int t = __shfl_up_sync(0xffffffffu, x, off);
        if (lane >= off) x += t;
    }
    if (lane == 31) wsum[wid] = x;
    __syncthreads();
    if (wid == 0) {
        int s = wsum[lane];
#pragma unroll
        for (int off = 1; off < 32; off <<= 1) {
            int t = __shfl_up_sync(0xffffffffu, s, off);
            if (lane >= off) s += t;
        }
        wpre[lane] = s;
    }
    __syncthreads();
    int base = wid ? wpre[wid - 1] : 0;
    if (i < N_DST) g_start[i] = base + x - v;
    if (tid == 0) g_bsum[blockIdx.x] = wpre[31];
}
__global__ void __launch_bounds__(1024) scan3_kernel() {
    __shared__ int sbs[40];
    __shared__ int sbase;
    int tid = threadIdx.x;
    if (tid < 40) sbs[tid] = g_bsum[tid];
    __syncthreads();
    if (tid == 0) {
        int a = 0;
        int b = blockIdx.x;
        for (int t = 0; t < b; t++) a += sbs[t];
        sbase = a;
    }
    __syncthreads();
    int i = blockIdx.x * 1024 + tid;
    if (i < N_DST) {
        int st = g_start[i] + sbase;
        g_start[i] = st;
        g_cur[i]   = st;
    }
}

// ---------------- K5: fill || edge (grid-merged; fill hides under edge) ----------------
#define FILL_BLOCKS 625

struct SmemEdge {
    unsigned sT[128][36];   // tfidf bf16 pairs [edge][kpair]
    unsigned sW[32][72];    // W_feat bf16 pairs [kpair][n]
    unsigned sZ[128][36];   // src z bf16 pairs [edge][pair], cols 0..31
    unsigned sZD[128][36];  // dst z bf16 pairs [edge][pair], cols 0..31
    float    sP[128][2];    // partial logit dots per n-half
};

__device__ __forceinline__ void do_fill(const int* __restrict__ dst,
                                        const int* __restrict__ src, int b, int tid) {
    // 512 threads x 4 edges: 625 * 2048 = 1,280,000 exactly
    int i0 = b * 2048 + tid;
    int i1 = i0 + 512, i2 = i0 + 1024, i3 = i0 + 1536;
    int d0 = dst[i0], d1 = dst[i1], d2 = dst[i2], d3 = dst[i3];
    int s0 = src[i0], s1 = src[i1], s2 = src[i2], s3 = src[i3];
    int p0 = atomicAdd(&g_cur[d0], 1);
    int p1 = atomicAdd(&g_cur[d1], 1);
    int p2 = atomicAdd(&g_cur[d2], 1);
    int p3 = atomicAdd(&g_cur[d3], 1);
    g_eid[p0] = i0; g_srcs[p0] = s0;
    g_eid[p1] = i1; g_srcs[p1] = s1;
    g_eid[p2] = i2; g_srcs[p2] = s2;
    g_eid[p3] = i3; g_srcs[p3] = s3;
}

__device__ __forceinline__ void do_edge(const float* __restrict__ tfidf,
                                        const float* __restrict__ bfeat,
                                        const float* __restrict__ Wattn,
                                        const int* __restrict__ esrc,
                                        const int* __restrict__ edst,
                                        SmemEdge& sm, int eb, int tid) {
    int base = eb * 128;

    for (int i = tid; i < 32 * 64; i += 512)
        sm.sW[i >> 6][i & 63] = g_Wfb[i];

    // tfidf rows: sequential (edge order)
    for (int i = tid; i < 128 * 16; i += 512) {
        int row = i >> 4, c4 = i & 15;
        float4 v = *(const float4*)&tfidf[(size_t)(base + row) * FEAT + c4 * 4];
        sm.sT[row][c4 * 2]     = pack_bf16(v.x, v.y);
        sm.sT[row][c4 * 2 + 1] = pack_bf16(v.z, v.w);
    }
    // src z rows (gather by esrc; L2/L1-resident)
    for (int i = tid; i < 128 * 8; i += 512) {
        int end = i >> 3, c = i & 7;
        int s = esrc[base + end];
        uint4 v = *(const uint4*)&g_zsrc_h[(size_t)s * 32 + c * 4];
        *(uint4*)&sm.sZ[end][c * 4] = v;
    }
    // dst z rows (gather by edst)
    for (int i = tid; i < 128 * 8; i += 512) {
        int end = i >> 3, c = i & 7;
        int d = edst[base + end];
        uint4 v = *(const uint4*)&g_zdst_h[(size_t)d * 32 + c * 4];
        *(uint4*)&sm.sZD[end][c * 4] = v;
    }
    __syncthreads();

    int lane = tid & 31, warp = tid >> 5;
    int g = lane >> 2, qp = lane & 3;
    int mt = warp & 7;
    int nh = warp >> 3;
    int wb = mt * 16;

    float acc[4][4];
#pragma unroll
    for (int nt = 0; nt < 4; nt++)
        acc[nt][0] = acc[nt][1] = acc[nt][2] = acc[nt][3] = 0.f;

#pragma unroll
    for (int kt = 0; kt < 4; kt++) {
        unsigned a0 = sm.sT[wb + g][kt * 8 + qp];
        unsigned a1 = sm.sT[wb + g + 8][kt * 8 + qp];
        unsigned a2 = sm.sT[wb + g][kt * 8 + qp + 4];
        unsigned a3 = sm.sT[wb + g + 8][kt * 8 + qp + 4];
#pragma unroll
        for (int nt = 0; nt < 4; nt++) {
            int nn = (nh * 4 + nt) * 8 + g;
            unsigned b0 = sm.sW[kt * 8 + qp][nn];
            unsigned b1 = sm.sW[kt * 8 + qp + 4][nn];
            MMA_BF16(acc[nt], a0, a1, a2, a3, b0, b1);
        }
    }

    float p0 = 0.f, p1 = 0.f;
#pragma unroll
    for (int nt = 0; nt < 4; nt++) {
        int col  = (nh * 4 + nt) * 8 + qp * 2;
        int pair = col >> 1;
        float2 bf  = *(const float2*)&bfeat[col];
        float2 wa  = *(const float2*)&Wattn[col];
        float2 zs0 = unpack_bf16(sm.sZ[wb + g][pair]);
        float2 zs1 = unpack_bf16(sm.sZ[wb + g + 8][pair]);
        float2 zd0 = unpack_bf16(sm.sZD[wb + g][pair]);
        float2 zd1 = unpack_bf16(sm.sZD[wb + g + 8][pair]);
        float v;
        v = acc[nt][0] + zs0.x + zd0.x + bf.x; v = v > 0.f ? v : 0.01f * v; p0 += v * wa.x;
        v = acc[nt][1] + zs0.y + zd0.y + bf.y; v = v > 0.f ? v : 0.01f * v; p0 += v * wa.y;
        v = acc[nt][2] + zs1.x + zd1.x + bf.x; v = v > 0.f ? v : 0.01f * v; p1 += v * wa.x;
        v = acc[nt][3] + zs1.y + zd1.y + bf.y; v = v > 0.f ? v : 0.01f * v; p1 += v * wa.y;
    }
    p0 += __shfl_xor_sync(0xffffffffu, p0, 1);
    p0 += __shfl_xor_sync(0xffffffffu, p0, 2);
    p1 += __shfl_xor_sync(0xffffffffu, p1, 1);
    p1 += __shfl_xor_sync(0xffffffffu, p1, 2);
    if (qp == 0) {
        sm.sP[wb + g][nh]     = p0;
        sm.sP[wb + g + 8][nh] = p1;
    }
    __syncthreads();
    if (tid < 128)
        g_e[base + tid] = __expf(sm.sP[tid][0] + sm.sP[tid][1]);  // EDGE-order store
}

__global__ void __launch_bounds__(512, 3) fill_edge_kernel(const float* __restrict__ tfidf,
                                                           const float* __restrict__ bfeat,
                                                           const float* __restrict__ Wattn,
                                                           const int* __restrict__ esrc,
                                                           const int* __restrict__ edst) {
    extern __shared__ char smem_raw[];
    int b = blockIdx.x, tid = threadIdx.x;
    if (b < FILL_BLOCKS) {
        do_fill(edst, esrc, b, tid);
    } else {
        do_edge(tfidf, bfeat, Wattn, esrc, edst, *(SmemEdge*)smem_raw, b - FILL_BLOCKS, tid);
    }
}

// ---------------- agg: softmax + weighted sum (warp per dst; logit via eid gather) ----------------
__global__ void __launch_bounds__(256) agg_kernel(float* __restrict__ out) {
    int w    = (blockIdx.x * blockDim.x + threadIdx.x) >> 5;
    int lane = threadIdx.x & 31;
    if (w >= N_DST) return;
    int start = g_start[w];
    int deg   = g_cnt[w];

    float denom = 0.f, accx = 0.f, accy = 0.f;
    for (int j0 = 0; j0 < deg; j0 += 32) {
        int j = j0 + lane;
        float we = 0.f;
        int s = 0;
        if (j < deg) {
            we = g_e[g_eid[start + j]];   // eid coalesced; logit 4B gather
            s  = g_srcs[start + j];
        }
        denom += we;
        int n = min(32, deg - j0);
        int k = 0;
        for (; k + 4 <= n; k += 4) {
            float a0 = __shfl_sync(0xffffffffu, we, k);
            float a1 = __shfl_sync(0xffffffffu, we, k + 1);
            float a2 = __shfl_sync(0xffffffffu, we, k + 2);
            float a3 = __shfl_sync(0xffffffffu, we, k + 3);
            int ss0 = __shfl_sync(0xffffffffu, s, k);
            int ss1 = __shfl_sync(0xffffffffu, s, k + 1);
            int ss2 = __shfl_sync(0xffffffffu, s, k + 2);
            int ss3 = __shfl_sync(0xffffffffu, s, k + 3);
            float2 z0 = *(const float2*)&g_zsrc[(size_t)ss0 * D + 2 * lane];
            float2 z1 = *(const float2*)&g_zsrc[(size_t)ss1 * D + 2 * lane];
            float2 z2 = *(const float2*)&g_zsrc[(size_t)ss2 * D + 2 * lane];
            float2 z3 = *(const float2*)&g_zsrc[(size_t)ss3 * D + 2 * lane];
            accx += a0 * z0.x + a1 * z1.x + a2 * z2.x + a3 * z3.x;
            accy += a0 * z0.y + a1 * z1.y + a2 * z2.y + a3 * z3.y;
        }
        for (; k < n; k++) {
            float a = __shfl_sync(0xffffffffu, we, k);
            int  ss = __shfl_sync(0xffffffffu, s, k);
            float2 z = *(const float2*)&g_zsrc[(size_t)ss * D + 2 * lane];
            accx += a * z.x;
            accy += a * z.y;
        }
    }
#pragma unroll
    for (int off = 16; off; off >>= 1) denom += __shfl_xor_sync(0xffffffffu, denom, off);
    float inv = 1.0f / fmaxf(denom, 1e-9f);
    *(float2*)&out[(size_t)w * D + 2 * lane] = make_float2(accx * inv, accy * inv);
}

// ---------------- launch ----------------
extern "C" void kernel_launch(void* const* d_in, const int* in_sizes, int n_in,
                              void* d_out, int out_size) {
    const float* h      = (const float*)d_in[0];
    const float* o      = (const float*)d_in[1];
    const float* tfidf  = (const float*)d_in[2];
    const float* W_fc   = (const float*)d_in[3];
    const float* W_fc1  = (const float*)d_in[4];
    const float* W_feat = (const float*)d_in[5];
    const float* b_feat = (const float*)d_in[6];
    const float* W_attn = (const float*)d_in[7];
    const int* esrc     = (const int*)d_in[8];
    const int* edst     = (const int*)d_in[9];
    float* out = (float*)d_out;

    static bool attr_set = false;
    if (!attr_set) {
        cudaFuncSetAttribute(fill_edge_kernel, cudaFuncAttributeMaxDynamicSharedMemorySize,
                             (int)sizeof(SmemEdge));
        attr_set = true;
    }

    setup_kernel<<<203, 256>>>(W_feat, W_fc1);
    fused_k2_kernel<<<CB_COUNT + CB_ZSRC + CB_ZDST, 256>>>(edst, h, W_fc, o);
    scan1_kernel<<<40, 1024>>>();
    scan3_kernel<<<40, 1024>>>();
    fill_edge_kernel<<<FILL_BLOCKS + NE / 128, 512, sizeof(SmemEdge)>>>(
        tfidf, b_feat, W_attn, esrc, edst);
    agg_kernel<<<(N_DST * 32 + 255) / 256, 256>>>(out);
}

// round 17
// speedup vs baseline: 1.1020x; 1.0295x over previous
#include <cuda_runtime.h>
#include <cuda_bf16.h>
#include <math.h>

#define N_SRC 10000
#define N_DST 40000
#define NE    1280000
#define IN_DIM 128
#define O_DIM  300
#define FEAT   64
#define D      64

// ---------------- scratch (static device globals) ----------------
__device__ float    g_zsrc[N_SRC * D];
__device__ unsigned g_zsrc_h[N_SRC * 32];   // bf16x2 pairs (L2-resident)
__device__ unsigned g_zdst_h[N_DST * 32];   // bf16x2 pairs (L2-resident)
__device__ float    g_e[NE];                // exp(logit) in EDGE order
__device__ int      g_cnt[N_DST];
__device__ int      g_start[N_DST];
__device__ int      g_cur[N_DST];
__device__ int2     g_pair[NE];             // csr position -> (edge id, src id)
__device__ int      g_bsum[64];
__device__ unsigned g_Wfb[32 * 64];         // W_feat bf16 pairs [kpair][n]
__device__ unsigned g_Wfb1[152 * 64];       // W_fc1 bf16 pairs, k padded

__device__ __forceinline__ unsigned pack_bf16(float lo, float hi) {
    unsigned u;
    asm("cvt.rn.bf16x2.f32 %0, %1, %2;" : "=r"(u) : "f"(hi), "f"(lo));
    return u;
}
__device__ __forceinline__ float2 unpack_bf16(unsigned u) {
    __nv_bfloat162 b = *(__nv_bfloat162*)&u;
    return __bfloat1622float2(b);
}

#define MMA_BF16(acc, a0, a1, a2, a3, b0, b1)                                        \
    asm volatile("mma.sync.aligned.m16n8k16.row.col.f32.bf16.bf16.f32 "              \
                 "{%0,%1,%2,%3}, {%4,%5,%6,%7}, {%8,%9}, {%0,%1,%2,%3};"             \
                 : "+f"(acc[0]), "+f"(acc[1]), "+f"(acc[2]), "+f"(acc[3])            \
                 : "r"(a0), "r"(a1), "r"(a2), "r"(a3), "r"(b0), "r"(b1))

// ---------------- K1: setup = zero cnt + pack weights ----------------
__global__ void __launch_bounds__(256) setup_kernel(const float* __restrict__ Wfeat,
                                                    const float* __restrict__ Wfc1) {
    int b = blockIdx.x;
    int tid = threadIdx.x;
    if (b < 157) {
        int i = b * 256 + tid;
        if (i < N_DST) g_cnt[i] = 0;
    } else if (b < 165) {
        int i = (b - 157) * 256 + tid;
        int kp = i >> 6, n = i & 63;
        g_Wfb[i] = pack_bf16(Wfeat[(2 * kp) * 64 + n], Wfeat[(2 * kp + 1) * 64 + n]);
    } else {
        int i = (b - 165) * 256 + tid;
        if (i < 152 * 64) {
            int kp = i >> 6, n = i & 63;
            int k0 = 2 * kp, k1 = 2 * kp + 1;
            float lo = (k0 < O_DIM) ? Wfc1[k0 * 64 + n] : 0.f;
            float hi = (k1 < O_DIM) ? Wfc1[k1 * 64 + n] : 0.f;
            g_Wfb1[i] = pack_bf16(lo, hi);
        }
    }
}

// ---------------- K2: count(4-way MLP) || zsrc || zdst (grid-merged) ----------------
#define CB_COUNT 1250
#define CB_ZSRC  625
#define CB_ZDST  625

struct SmemZsrc { float sW[IN_DIM][D]; float sh[16][IN_DIM]; };
struct SmemZdst { unsigned sA[64][84]; unsigned sW[80][72]; };
union SmemK2 { SmemZsrc zs; SmemZdst zd; };

__device__ __forceinline__ void do_zsrc(const float* __restrict__ h,
                                        const float* __restrict__ W,
                                        SmemZsrc& sm, int b, int tid) {
    int r0 = b * 16;
    for (int i = tid; i < IN_DIM * D / 4; i += 256)
        ((float4*)&sm.sW[0][0])[i] = ((const float4*)W)[i];
    for (int i = tid; i < 16 * IN_DIM / 4; i += 256)
        ((float4*)&sm.sh[0][0])[i] = ((const float4*)(h + (size_t)r0 * IN_DIM))[i];
    __syncthreads();
    int d4 = (tid & 15) * 4;
    int r  = tid >> 4;
    float a0 = 0.f, a1 = 0.f, a2 = 0.f, a3 = 0.f;
#pragma unroll 8
    for (int k = 0; k < IN_DIM; k++) {
        float hv = sm.sh[r][k];
        float4 w = *(const float4*)&sm.sW[k][d4];
        a0 += hv * w.x; a1 += hv * w.y; a2 += hv * w.z; a3 += hv * w.w;
    }
    int node = r0 + r;
    *(float4*)&g_zsrc[(size_t)node * D + d4] = make_float4(a0, a1, a2, a3);
    *(uint2*)&g_zsrc_h[(size_t)node * 32 + d4 / 2] =
        make_uint2(pack_bf16(a0, a1), pack_bf16(a2, a3));
}

__device__ __forceinline__ void do_zdst(const float* __restrict__ o,
                                        SmemZdst& sm, int b, int tid) {
    int lane = tid & 31, warp = tid >> 5;
    int r0 = b * 64;
    int g = lane >> 2, qp = lane & 3;
    int mt = warp & 3;
    int nh = warp >> 2;

    float acc[4][4];
#pragma unroll
    for (int nt = 0; nt < 4; nt++)
        acc[nt][0] = acc[nt][1] = acc[nt][2] = acc[nt][3] = 0.f;

    for (int c = 0; c < 2; c++) {
        int kp0 = c * 80;
        __syncthreads();
        for (int i = tid; i < 64 * 80; i += 256) {
            int row = i / 80, kp = i % 80;
            int gkp = kp0 + kp;
            float lo = 0.f, hi = 0.f;
            if (gkp < 150) {
                float2 v = *(const float2*)&o[(size_t)(r0 + row) * O_DIM + gkp * 2];
                lo = v.x; hi = v.y;
            }
            sm.sA[row][kp] = pack_bf16(lo, hi);
        }
        int npair = c ? 72 : 80;
        for (int i = tid; i < npair * 64; i += 256) {
            int kp = i >> 6, n = i & 63;
            sm.sW[kp][n] = g_Wfb1[(kp0 + kp) * 64 + n];
        }
        __syncthreads();
        int nkt = c ? 9 : 10;
        for (int lt = 0; lt < nkt; lt++) {
            unsigned a0 = sm.sA[mt * 16 + g][lt * 8 + qp];
            unsigned a1 = sm.sA[mt * 16 + g + 8][lt * 8 + qp];
            unsigned a2 = sm.sA[mt * 16 + g][lt * 8 + qp + 4];
            unsigned a3 = sm.sA[mt * 16 + g + 8][lt * 8 + qp + 4];
#pragma unroll
            for (int nt = 0; nt < 4; nt++) {
                int nn = (nh * 4 + nt) * 8 + g;
                unsigned b0 = sm.sW[lt * 8 + qp][nn];
                unsigned b1 = sm.sW[lt * 8 + qp + 4][nn];
                MMA_BF16(acc[nt], a0, a1, a2, a3, b0, b1);
            }
        }
    }
    int row0 = r0 + mt * 16 + g;
#pragma unroll
    for (int nt = 0; nt < 4; nt++) {
        int pair = (nh * 4 + nt) * 4 + qp;
        g_zdst_h[(size_t)row0 * 32 + pair]       = pack_bf16(acc[nt][0], acc[nt][1]);
        g_zdst_h[(size_t)(row0 + 8) * 32 + pair] = pack_bf16(acc[nt][2], acc[nt][3]);
    }
}

__global__ void __launch_bounds__(256) fused_k2_kernel(const int* __restrict__ edst,
                                                       const float* __restrict__ h,
                                                       const float* __restrict__ W_fc,
                                                       const float* __restrict__ o) {
    __shared__ SmemK2 sm;
    int b = blockIdx.x, tid = threadIdx.x;
    if (b < CB_COUNT) {
        // 4 edges/thread: 1250 * 1024 = NE exactly
        int i0 = b * 1024 + tid;
        int d0 = edst[i0], d1 = edst[i0 + 256], d2 = edst[i0 + 512], d3 = edst[i0 + 768];
        atomicAdd(&g_cnt[d0], 1);
        atomicAdd(&g_cnt[d1], 1);
        atomicAdd(&g_cnt[d2], 1);
        atomicAdd(&g_cnt[d3], 1);
    } else if (b < CB_COUNT + CB_ZSRC) {
        do_zsrc(h, W_fc, sm.zs, b - CB_COUNT, tid);
    } else {
        do_zdst(o, sm.zd, b - CB_COUNT - CB_ZSRC, tid);
    }
}

// ---------------- CSR scans ----------------
__global__ void __launch_bounds__(1024) scan1_kernel() {
    __shared__ int wsum[32];
    __shared__ int wpre[32];
    int tid = threadIdx.x, lane = tid & 31, wid = tid >> 5;
    int i = blockIdx.x * 1024 + tid;
    int v = (i < N_DST) ? g_cnt[i] : 0;
    int x = v;
#pragma unroll
    for (int off = 1; off < 32; off <<= 1) {
        int t = __shfl_up_sync(0xffffffffu, x, off);
        if (lane >= off) x += t;
    }
    if (lane == 31) wsum[wid] = x;
    __syncthreads();
    if (wid == 0) {
        int s = wsum[lane];
#pragma unroll
        for (int off = 1; off < 32; off <<= 1) {
            int t = __shfl_up_sync(0xffffffffu, s, off);
            if (lane >= off) s += t;
        }
        wpre[lane] = s;
    }
    __syncthreads();
    int base = wid ? wpre[wid - 1] : 0;
    if (i < N_DST) g_start[i] = base + x - v;
    if (tid == 0) g_bsum[blockIdx.x] = wpre[31];
}
__global__ void __launch_bounds__(1024) scan3_kernel() {
    __shared__ int sbs[40];
    __shared__ int sbase;
    int tid = threadIdx.x;
    if (tid < 40) sbs[tid] = g_bsum[tid];
    __syncthreads();
    if (tid == 0) {
        int a = 0;
        int b = blockIdx.x;
        for (int t = 0; t < b; t++) a += sbs[t];
        sbase = a;
    }
    __syncthreads();
    int i = blockIdx.x * 1024 + tid;
    if (i < N_DST) {
        int st = g_start[i] + sbase;
        g_start[i] = st;
        g_cur[i]   = st;
    }
}

// ---------------- K5: fill || edge (grid-merged; fill hides under edge) ----------------
#define FILL_BLOCKS 625

struct SmemEdge {
    unsigned sT[128][36];   // tfidf bf16 pairs [edge][kpair]
    unsigned sW[32][72];    // W_feat bf16 pairs [kpair][n]
    unsigned sZ[128][36];   // src z bf16 pairs [edge][pair], cols 0..31
    unsigned sZD[128][36];  // dst z bf16 pairs [edge][pair], cols 0..31
    float    sP[128][2];    // partial logit dots per n-half
};

__device__ __forceinline__ void do_fill(const int* __restrict__ dst,
                                        const int* __restrict__ src, int b, int tid) {
    // 512 threads x 4 edges: 625 * 2048 = 1,280,000 exactly
    int i0 = b * 2048 + tid;
    int i1 = i0 + 512, i2 = i0 + 1024, i3 = i0 + 1536;
    int d0 = dst[i0], d1 = dst[i1], d2 = dst[i2], d3 = dst[i3];
    int s0 = src[i0], s1 = src[i1], s2 = src[i2], s3 = src[i3];
    int p0 = atomicAdd(&g_cur[d0], 1);
    int p1 = atomicAdd(&g_cur[d1], 1);
    int p2 = atomicAdd(&g_cur[d2], 1);
    int p3 = atomicAdd(&g_cur[d3], 1);
    g_pair[p0] = make_int2(i0, s0);    // single 8B scatter per edge
    g_pair[p1] = make_int2(i1, s1);
    g_pair[p2] = make_int2(i2, s2);
    g_pair[p3] = make_int2(i3, s3);
}

__device__ __forceinline__ void do_edge(const float* __restrict__ tfidf,
                                        const float* __restrict__ bfeat,
                                        const float* __restrict__ Wattn,
                                        const int* __restrict__ esrc,
                                        const int* __restrict__ edst,
                                        SmemEdge& sm, int eb, int tid) {
    int base = eb * 128;

    for (int i = tid; i < 32 * 64; i += 512)
        sm.sW[i >> 6][i & 63] = g_Wfb[i];

    // tfidf rows: sequential (edge order)
    for (int i = tid; i < 128 * 16; i += 512) {
        int row = i >> 4, c4 = i & 15;
        float4 v = *(const float4*)&tfidf[(size_t)(base + row) * FEAT + c4 * 4];
        sm.sT[row][c4 * 2]     = pack_bf16(v.x, v.y);
        sm.sT[row][c4 * 2 + 1] = pack_bf16(v.z, v.w);
    }
    // src z rows (gather by esrc; L2/L1-resident)
    for (int i = tid; i < 128 * 8; i += 512) {
        int end = i >> 3, c = i & 7;
        int s = esrc[base + end];
        uint4 v = *(const uint4*)&g_zsrc_h[(size_t)s * 32 + c * 4];
        *(uint4*)&sm.sZ[end][c * 4] = v;
    }
    // dst z rows (gather by edst)
    for (int i = tid; i < 128 * 8; i += 512) {
        int end = i >> 3, c = i & 7;
        int d = edst[base + end];
        uint4 v = *(const uint4*)&g_zdst_h[(size_t)d * 32 + c * 4];
        *(uint4*)&sm.sZD[end][c * 4] = v;
    }
    __syncthreads();

    int lane = tid & 31, warp = tid >> 5;
    int g = lane >> 2, qp = lane & 3;
    int mt = warp & 7;
    int nh = warp >> 3;
    int wb = mt * 16;

    float acc[4][4];
#pragma unroll
    for (int nt = 0; nt < 4; nt++)
        acc[nt][0] = acc[nt][1] = acc[nt][2] = acc[nt][3] = 0.f;

#pragma unroll
    for (int kt = 0; kt < 4; kt++) {
        unsigned a0 = sm.sT[wb + g][kt * 8 + qp];
        unsigned a1 = sm.sT[wb + g + 8][kt * 8 + qp];
        unsigned a2 = sm.sT[wb + g][kt * 8 + qp + 4];
        unsigned a3 = sm.sT[wb + g + 8][kt * 8 + qp + 4];
#pragma unroll
        for (int nt = 0; nt < 4; nt++) {
            int nn = (nh * 4 + nt) * 8 + g;
            unsigned b0 = sm.sW[kt * 8 + qp][nn];
            unsigned b1 = sm.sW[kt * 8 + qp + 4][nn];
            MMA_BF16(acc[nt], a0, a1, a2, a3, b0, b1);
        }
    }

    float p0 = 0.f, p1 = 0.f;
#pragma unroll
    for (int nt = 0; nt < 4; nt++) {
        int col  = (nh * 4 + nt) * 8 + qp * 2;
        int pair = col >> 1;
        float2 bf  = *(const float2*)&bfeat[col];
        float2 wa  = *(const float2*)&Wattn[col];
        float2 zs0 = unpack_bf16(sm.sZ[wb + g][pair]);
        float2 zs1 = unpack_bf16(sm.sZ[wb + g + 8][pair]);
        float2 zd0 = unpack_bf16(sm.sZD[wb + g][pair]);
        float2 zd1 = unpack_bf16(sm.sZD[wb + g + 8][pair]);
        float v;
        v = acc[nt][0] + zs0.x + zd0.x + bf.x; v = v > 0.f ? v : 0.01f * v; p0 += v * wa.x;
        v = acc[nt][1] + zs0.y + zd0.y + bf.y; v = v > 0.f ? v : 0.01f * v; p0 += v * wa.y;
        v = acc[nt][2] + zs1.x + zd1.x + bf.x; v = v > 0.f ? v : 0.01f * v; p1 += v * wa.x;
        v = acc[nt][3] + zs1.y + zd1.y + bf.y; v = v > 0.f ? v : 0.01f * v; p1 += v * wa.y;
    }
    p0 += __shfl_xor_sync(0xffffffffu, p0, 1);
    p0 += __shfl_xor_sync(0xffffffffu, p0, 2);
    p1 += __shfl_xor_sync(0xffffffffu, p1, 1);
    p1 += __shfl_xor_sync(0xffffffffu, p1, 2);
    if (qp == 0) {
        sm.sP[wb + g][nh]     = p0;
        sm.sP[wb + g + 8][nh] = p1;
    }
    __syncthreads();
    if (tid < 128)
        g_e[base + tid] = __expf(sm.sP[tid][0] + sm.sP[tid][1]);  // EDGE-order store
}

__global__ void __launch_bounds__(512, 3) fill_edge_kernel(const float* __restrict__ tfidf,
                                                           const float* __restrict__ bfeat,
                                                           const float* __restrict__ Wattn,
                                                           const int* __restrict__ esrc,
                                                           const int* __restrict__ edst) {
    extern __shared__ char smem_raw[];
    int b = blockIdx.x, tid = threadIdx.x;
    if (b < FILL_BLOCKS) {
        do_fill(edst, esrc, b, tid);
    } else {
        do_edge(tfidf, bfeat, Wattn, esrc, edst, *(SmemEdge*)smem_raw, b - FILL_BLOCKS, tid);
    }
}

// ---------------- agg: softmax + weighted sum (warp per dst) ----------------
__global__ void __launch_bounds__(256) agg_kernel(float* __restrict__ out) {
    int w    = (blockIdx.x * blockDim.x + threadIdx.x) >> 5;
    int lane = threadIdx.x & 31;
    if (w >= N_DST) return;
    int start = g_start[w];
    int deg   = g_cnt[w];

    float denom = 0.f, accx = 0.f, accy = 0.f;
    for (int j0 = 0; j0 < deg; j0 += 32) {
        int j = j0 + lane;
        float we = 0.f;
        int s = 0;
        if (j < deg) {
            int2 es = g_pair[start + j];   // coalesced 8B
            we = g_e[es.x];                // 4B gather
            s  = es.y;
        }
        denom += we;
        int n = min(32, deg - j0);
        int k = 0;
        for (; k + 4 <= n; k += 4) {
            float a0 = __shfl_sync(0xffffffffu, we, k);
            float a1 = __shfl_sync(0xffffffffu, we, k + 1);
            float a2 = __shfl_sync(0xffffffffu, we, k + 2);
            float a3 = __shfl_sync(0xffffffffu, we, k + 3);
            int ss0 = __shfl_sync(0xffffffffu, s, k);
            int ss1 = __shfl_sync(0xffffffffu, s, k + 1);
            int ss2 = __shfl_sync(0xffffffffu, s, k + 2);
            int ss3 = __shfl_sync(0xffffffffu, s, k + 3);
            float2 z0 = *(const float2*)&g_zsrc[(size_t)ss0 * D + 2 * lane];
            float2 z1 = *(const float2*)&g_zsrc[(size_t)ss1 * D + 2 * lane];
            float2 z2 = *(const float2*)&g_zsrc[(size_t)ss2 * D + 2 * lane];
            float2 z3 = *(const float2*)&g_zsrc[(size_t)ss3 * D + 2 * lane];
            accx += a0 * z0.x + a1 * z1.x + a2 * z2.x + a3 * z3.x;
            accy += a0 * z0.y + a1 * z1.y + a2 * z2.y + a3 * z3.y;
        }
        for (; k < n; k++) {
            float a = __shfl_sync(0xffffffffu, we, k);
            int  ss = __shfl_sync(0xffffffffu, s, k);
            float2 z = *(const float2*)&g_zsrc[(size_t)ss * D + 2 * lane];
            accx += a * z.x;
            accy += a * z.y;
        }
    }
#pragma unroll
    for (int off = 16; off; off >>= 1) denom += __shfl_xor_sync(0xffffffffu, denom, off);
    float inv = 1.0f / fmaxf(denom, 1e-9f);
    *(float2*)&out[(size_t)w * D + 2 * lane] = make_float2(accx * inv, accy * inv);
}

// ---------------- launch ----------------
extern "C" void kernel_launch(void* const* d_in, const int* in_sizes, int n_in,
                              void* d_out, int out_size) {
    const float* h      = (const float*)d_in[0];
    const float* o      = (const float*)d_in[1];
    const float* tfidf  = (const float*)d_in[2];
    const float* W_fc   = (const float*)d_in[3];
    const float* W_fc1  = (const float*)d_in[4];
    const float* W_feat = (const float*)d_in[5];
    const float* b_feat = (const float*)d_in[6];
    const float* W_attn = (const float*)d_in[7];
    const int* esrc     = (const int*)d_in[8];
    const int* edst     = (const int*)d_in[9];
    float* out = (float*)d_out;

    static bool attr_set = false;
    if (!attr_set) {
        cudaFuncSetAttribute(fill_edge_kernel, cudaFuncAttributeMaxDynamicSharedMemorySize,
                             (int)sizeof(SmemEdge));
        attr_set = true;
    }

    setup_kernel<<<203, 256>>>(W_feat, W_fc1);
    fused_k2_kernel<<<CB_COUNT + CB_ZSRC + CB_ZDST, 256>>>(edst, h, W_fc, o);
    scan1_kernel<<<40, 1024>>>();
    scan3_kernel<<<40, 1024>>>();
    fill_edge_kernel<<<FILL_BLOCKS + NE / 128, 512, sizeof(SmemEdge)>>>(
        tfidf, b_feat, W_attn, esrc, edst);
    agg_kernel<<<(N_DST * 32 + 255) / 256, 256>>>(out);
}